// round 4
// baseline (speedup 1.0000x reference)
#include <cuda_runtime.h>

#define BSZ 2048
#define LSZ 200
#define DSZ 256
#define ATTN_GRID 512   // persistent: 2048 / 512 = 4 batches per CTA

// Scratch (device globals — no allocation allowed). Kernels reference these
// directly; kernel_launch contains ONLY kernel launches (graph-capture safe).
__device__ float g_M[DSZ * DSZ];     // M = W_query @ W_key^T  (row-major [e][d])
__device__ float g_QK[BSZ * DSZ];    // q @ M
__device__ float g_CTX[BSZ * DSZ];   // softmax-weighted sum of k rows

// ---------------------------------------------------------------------------
// g_M[i][j] = Wq[i,:] . Wk[j,:]   (dot-product form handles the B^T naturally)
// grid = 256 CTAs (one per output row i), 256 threads = 8 warps,
// warp w covers cols [w*32, w*32+32).
// ---------------------------------------------------------------------------
__global__ void wmat_kernel(const float* __restrict__ Wq,
                            const float* __restrict__ Wk)
{
    const int i = blockIdx.x;
    const int w = threadIdx.x >> 5;
    const int lane = threadIdx.x & 31;

    // A row slice: dims [lane*8, lane*8+8)
    const float4* ap = (const float4*)(Wq + i * 256 + lane * 8);
    const float4 a0 = ap[0];
    const float4 a1 = ap[1];

    float res = 0.0f;
    #pragma unroll 4
    for (int jj = 0; jj < 32; jj++) {
        const int j = w * 32 + jj;
        const float4* bp = (const float4*)(Wk + j * 256 + lane * 8);
        const float4 b0 = __ldg(bp);
        const float4 b1 = __ldg(bp + 1);
        float d = a0.x * b0.x + a0.y * b0.y + a0.z * b0.z + a0.w * b0.w
                + a1.x * b1.x + a1.y * b1.y + a1.z * b1.z + a1.w * b1.w;
        #pragma unroll
        for (int off = 16; off > 0; off >>= 1)
            d += __shfl_xor_sync(0xffffffffu, d, off);
        if (lane == jj) res = d;
    }
    g_M[i * 256 + w * 32 + lane] = res;
}

// ---------------------------------------------------------------------------
// rowgemm: C[R,256] = A[R,256] @ B[256,256]  (all row-major)
// CTA: 256 threads = 8 warps. Warp handles 4 rows x 128 cols; lane owns 4
// consecutive cols (one float4 accumulator per row). No __syncthreads in the
// mainloop; 16 independent FFMAs per B load -> latency-tolerant at 8 warps/SM.
// grid = (R/32, 2).
// ---------------------------------------------------------------------------
__device__ __forceinline__ void rowgemm_body(const float* __restrict__ A,
                                             const float* __restrict__ B,
                                             float* __restrict__ C)
{
    __shared__ float sA[8][4][256];
    const int w = threadIdx.x >> 5;
    const int lane = threadIdx.x & 31;
    const int row0 = blockIdx.x * 32 + w * 4;
    const int col = blockIdx.y * 128 + lane * 4;

    // warp-private A staging: 4 rows x 256 floats = 64 float4 per row
    #pragma unroll
    for (int r = 0; r < 4; r++) {
        const float4* src = (const float4*)(A + (size_t)(row0 + r) * 256);
        float4* dst = (float4*)sA[w][r];
        dst[lane] = src[lane];
        dst[lane + 32] = src[lane + 32];
    }
    __syncwarp();

    float4 acc0 = {0.f, 0.f, 0.f, 0.f};
    float4 acc1 = {0.f, 0.f, 0.f, 0.f};
    float4 acc2 = {0.f, 0.f, 0.f, 0.f};
    float4 acc3 = {0.f, 0.f, 0.f, 0.f};

    const float* Bc = B + col;

    #pragma unroll 2
    for (int k0 = 0; k0 < 256; k0 += 4) {
        const float4 av0 = *(const float4*)&sA[w][0][k0];
        const float4 av1 = *(const float4*)&sA[w][1][k0];
        const float4 av2 = *(const float4*)&sA[w][2][k0];
        const float4 av3 = *(const float4*)&sA[w][3][k0];
        const float a0k[4] = {av0.x, av0.y, av0.z, av0.w};
        const float a1k[4] = {av1.x, av1.y, av1.z, av1.w};
        const float a2k[4] = {av2.x, av2.y, av2.z, av2.w};
        const float a3k[4] = {av3.x, av3.y, av3.z, av3.w};
        #pragma unroll
        for (int kk = 0; kk < 4; kk++) {
            const float4 bv = __ldg((const float4*)(Bc + (size_t)(k0 + kk) * 256));
            acc0.x += a0k[kk] * bv.x; acc0.y += a0k[kk] * bv.y;
            acc0.z += a0k[kk] * bv.z; acc0.w += a0k[kk] * bv.w;
            acc1.x += a1k[kk] * bv.x; acc1.y += a1k[kk] * bv.y;
            acc1.z += a1k[kk] * bv.z; acc1.w += a1k[kk] * bv.w;
            acc2.x += a2k[kk] * bv.x; acc2.y += a2k[kk] * bv.y;
            acc2.z += a2k[kk] * bv.z; acc2.w += a2k[kk] * bv.w;
            acc3.x += a3k[kk] * bv.x; acc3.y += a3k[kk] * bv.y;
            acc3.z += a3k[kk] * bv.z; acc3.w += a3k[kk] * bv.w;
        }
    }

    *(float4*)(C + (size_t)(row0 + 0) * 256 + col) = acc0;
    *(float4*)(C + (size_t)(row0 + 1) * 256 + col) = acc1;
    *(float4*)(C + (size_t)(row0 + 2) * 256 + col) = acc2;
    *(float4*)(C + (size_t)(row0 + 3) * 256 + col) = acc3;
}

// QK = q @ g_M
__global__ void qk_gemm_kernel(const float* __restrict__ q)
{
    rowgemm_body(q, g_M, g_QK);
}

// out = g_CTX @ Wv
__global__ void out_gemm_kernel(const float* __restrict__ Wv,
                                float* __restrict__ out)
{
    rowgemm_body(g_CTX, Wv, out);
}

// ---------------------------------------------------------------------------
// Attention in k-space (persistent CTAs). For each batch b:
//   score[l] = k[b,l] . QK[b] + bias*256
//   p[l]     = l<len ? exp(sigmoid(score)/16 - 1/16) : 0   (len==0 -> p=1)
//   CTX[b]   = (sum_l p[l]*k[b,l]) / (sum_l p[l])
// Fixed-max softmax is exact: valid logits in (0, 1/16]; masked PAD/16
// underflows to exactly 0. len==0 (all PAD) -> uniform weights.
// grid = ATTN_GRID, each CTA strides over BSZ/ATTN_GRID batches (one wave).
// ---------------------------------------------------------------------------
__global__ void __launch_bounds__(256, 4)
attn_kernel(const float* __restrict__ K,
            const int* __restrict__ keys_length,
            const float* __restrict__ bias)
{
    __shared__ float sZ[8];
    __shared__ float sctx[8][DSZ];

    const int tid = threadIdx.x;
    const int w = tid >> 5;
    const int lane = tid & 31;
    const float b256 = bias[0] * 256.0f;

    for (int b = blockIdx.x; b < BSZ; b += ATTN_GRID) {
        const float* kb = K + (size_t)b * LSZ * DSZ;

        // per-lane slice of QK[b]: dims [lane*8, lane*8+8)
        const float4* qkp = (const float4*)(g_QK + (size_t)b * DSZ + lane * 8);
        const float4 q0 = qkp[0];
        const float4 q1 = qkp[1];
        const int len = keys_length[b];

        float Z = 0.0f;
        float c0 = 0.f, c1 = 0.f, c2 = 0.f, c3 = 0.f;
        float c4 = 0.f, c5 = 0.f, c6 = 0.f, c7 = 0.f;

        #pragma unroll 5
        for (int i = 0; i < LSZ / 8; i++) {
            const int l = i * 8 + w;
            const float4* kr = (const float4*)(kb + l * DSZ + lane * 8);
            const float4 a0 = __ldg(kr);
            const float4 a1 = __ldg(kr + 1);

            float dot = a0.x * q0.x + a0.y * q0.y + a0.z * q0.z + a0.w * q0.w
                      + a1.x * q1.x + a1.y * q1.y + a1.z * q1.z + a1.w * q1.w;
            #pragma unroll
            for (int off = 16; off > 0; off >>= 1)
                dot += __shfl_xor_sync(0xffffffffu, dot, off);

            float p;
            if (len == 0) {
                p = 1.0f;
            } else if (l < len) {
                const float score = dot + b256;
                const float sig = 1.0f / (1.0f + __expf(-score));
                p = __expf(sig * 0.0625f - 0.0625f);
            } else {
                p = 0.0f;
            }

            Z += p;
            c0 += p * a0.x; c1 += p * a0.y; c2 += p * a0.z; c3 += p * a0.w;
            c4 += p * a1.x; c5 += p * a1.y; c6 += p * a1.z; c7 += p * a1.w;
        }

        if (lane == 0) sZ[w] = Z;   // Z identical across lanes after butterfly
        const int d = lane * 8;
        sctx[w][d + 0] = c0; sctx[w][d + 1] = c1;
        sctx[w][d + 2] = c2; sctx[w][d + 3] = c3;
        sctx[w][d + 4] = c4; sctx[w][d + 5] = c5;
        sctx[w][d + 6] = c6; sctx[w][d + 7] = c7;
        __syncthreads();

        float zt = 0.0f;
        #pragma unroll
        for (int ww = 0; ww < 8; ww++) zt += sZ[ww];
        float c = 0.0f;
        #pragma unroll
        for (int ww = 0; ww < 8; ww++) c += sctx[ww][tid];

        g_CTX[(size_t)b * DSZ + tid] = c / zt;
        __syncthreads();   // protect sZ/sctx before next batch overwrites
    }
}

// ---------------------------------------------------------------------------
extern "C" void kernel_launch(void* const* d_in, const int* in_sizes, int n_in,
                              void* d_out, int out_size)
{
    const float* q      = (const float*)d_in[0];   // [2048, 1, 256]
    const float* k      = (const float*)d_in[1];   // [2048, 200, 256]
    // d_in[2] = v: unused (reference derives both score and value paths from k)
    const int*   klen   = (const int*)d_in[3];     // [2048, 1]
    const float* Wq     = (const float*)d_in[4];   // [256, 256]
    const float* Wk     = (const float*)d_in[5];   // [256, 256]
    const float* Wv     = (const float*)d_in[6];   // [256, 256]
    const float* bias   = (const float*)d_in[7];   // [1]
    float* out = (float*)d_out;                    // [2048, 1, 256]

    // 1) M = Wq @ Wk^T  (dot-product form, grid 256)
    wmat_kernel<<<256, 256>>>(Wq, Wk);
    // 2) QK = q @ M   [2048,256]
    qk_gemm_kernel<<<dim3(BSZ / 32, 2), 256>>>(q);
    // 3) attention in k-space -> CTX [2048,256]  (persistent, one wave)
    attn_kernel<<<ATTN_GRID, 256>>>(k, klen, bias);
    // 4) out = CTX @ Wv
    out_gemm_kernel<<<dim3(BSZ / 32, 2), 256>>>(Wv, out);
}

// round 6
// speedup vs baseline: 1.4017x; 1.4017x over previous
#include <cuda_runtime.h>

#define BSZ 2048
#define LSZ 200
#define DSZ 256
#define ATTN_GRID 512   // persistent: 2048 / 512 = 4 batches per CTA

// Scratch (device globals — no allocation allowed). Kernels reference these
// directly; kernel_launch contains ONLY kernel launches (graph-capture safe).
__device__ float g_M[DSZ * DSZ];     // M = W_query @ W_key^T
__device__ float g_QK[BSZ * DSZ];    // q @ M
__device__ float g_CTX[BSZ * DSZ];   // softmax-weighted sum of k rows

// ---------------------------------------------------------------------------
// g_M[i][j] = Wq[i,:] . Wk[j,:]
// grid = 256 CTAs (one per output row i), 256 threads = 8 warps,
// warp w covers cols [w*32, w*32+32).
// ---------------------------------------------------------------------------
__global__ void wmat_kernel(const float* __restrict__ Wq,
                            const float* __restrict__ Wk)
{
    const int i = blockIdx.x;
    const int w = threadIdx.x >> 5;
    const int lane = threadIdx.x & 31;

    const float4* ap = (const float4*)(Wq + i * 256 + lane * 8);
    const float4 a0 = ap[0];
    const float4 a1 = ap[1];

    float res = 0.0f;
    #pragma unroll 4
    for (int jj = 0; jj < 32; jj++) {
        const int j = w * 32 + jj;
        const float4* bp = (const float4*)(Wk + j * 256 + lane * 8);
        const float4 b0 = __ldg(bp);
        const float4 b1 = __ldg(bp + 1);
        float d = a0.x * b0.x + a0.y * b0.y + a0.z * b0.z + a0.w * b0.w
                + a1.x * b1.x + a1.y * b1.y + a1.z * b1.z + a1.w * b1.w;
        #pragma unroll
        for (int off = 16; off > 0; off >>= 1)
            d += __shfl_xor_sync(0xffffffffu, d, off);
        if (lane == jj) res = d;
    }
    g_M[i * 256 + w * 32 + lane] = res;
}

// ---------------------------------------------------------------------------
// Tiled GEMM: C[2048,256] = A[2048,256] @ B[256,256]  (row-major)
// BM=32, BN=32, BK=16, 128 threads/CTA, grid (64, 8) = 512 CTAs (~3.5/SM).
// Per thread: 4x2 micro-tile (8 acc), 1 float4 A-load + 1 float4 B-load and
// 128 FFMA per k-chunk. Small CTAs so barrier bubbles overlap across CTAs.
// ---------------------------------------------------------------------------
__device__ __forceinline__ void tgemm_body(const float* __restrict__ A,
                                           const float* __restrict__ B,
                                           float* __restrict__ C)
{
    __shared__ float As[16][32];   // [k][row]
    __shared__ float Bs[16][32];   // [k][col]
    const int tid = threadIdx.x;
    const int tx = tid & 15;       // col group: 2 cols
    const int ty = tid >> 4;       // row group: 4 rows (0..7)
    const int row0 = blockIdx.x * 32;
    const int col0 = blockIdx.y * 32;

    const int la_r = tid >> 2;           // A load: row 0..31
    const int la_k = (tid & 3) * 4;      // A load: k offset (float4)
    const int lb_k = tid >> 3;           // B load: k 0..15
    const int lb_c = (tid & 7) * 4;      // B load: col offset (float4)

    const float* Ap = A + (size_t)(row0 + la_r) * 256 + la_k;
    const float* Bp = B + (size_t)lb_k * 256 + col0 + lb_c;

    float acc[4][2] = {};
    #pragma unroll 1
    for (int k0 = 0; k0 < 256; k0 += 16) {
        const float4 a = *(const float4*)(Ap + k0);
        const float4 bvl = *(const float4*)(Bp + (size_t)k0 * 256);
        As[la_k + 0][la_r] = a.x;
        As[la_k + 1][la_r] = a.y;
        As[la_k + 2][la_r] = a.z;
        As[la_k + 3][la_r] = a.w;
        *(float4*)&Bs[lb_k][lb_c] = bvl;
        __syncthreads();
        #pragma unroll
        for (int kk = 0; kk < 16; kk++) {
            const float4 av = *(const float4*)&As[kk][ty * 4];
            const float2 bv = *(const float2*)&Bs[kk][tx * 2];
            acc[0][0] += av.x * bv.x; acc[0][1] += av.x * bv.y;
            acc[1][0] += av.y * bv.x; acc[1][1] += av.y * bv.y;
            acc[2][0] += av.z * bv.x; acc[2][1] += av.z * bv.y;
            acc[3][0] += av.w * bv.x; acc[3][1] += av.w * bv.y;
        }
        __syncthreads();
    }
    #pragma unroll
    for (int i = 0; i < 4; i++) {
        float2 v; v.x = acc[i][0]; v.y = acc[i][1];
        *(float2*)(C + (size_t)(row0 + ty * 4 + i) * 256 + col0 + tx * 2) = v;
    }
}

// QK = q @ g_M
__global__ void __launch_bounds__(128)
qk_gemm_kernel(const float* __restrict__ q)
{
    tgemm_body(q, g_M, g_QK);
}

// out = g_CTX @ Wv
__global__ void __launch_bounds__(128)
out_gemm_kernel(const float* __restrict__ Wv,
                float* __restrict__ out)
{
    tgemm_body(g_CTX, Wv, out);
}

// ---------------------------------------------------------------------------
// Attention in k-space (persistent CTAs). For each batch b:
//   score[l] = k[b,l] . QK[b] + bias*256
//   p[l]     = l<len ? exp(sigmoid(score)/16 - 1/16) : 0   (len==0 -> p=1)
//   CTX[b]   = (sum_l p[l]*k[b,l]) / (sum_l p[l])
// Fixed-max softmax is exact: valid logits in (0, 1/16]; masked PAD/16
// underflows to exactly 0. len==0 (all PAD) -> uniform weights.
// ---------------------------------------------------------------------------
__global__ void __launch_bounds__(256, 4)
attn_kernel(const float* __restrict__ K,
            const int* __restrict__ keys_length,
            const float* __restrict__ bias)
{
    __shared__ float sZ[8];
    __shared__ float sctx[8][DSZ];

    const int tid = threadIdx.x;
    const int w = tid >> 5;
    const int lane = tid & 31;
    const float b256 = bias[0] * 256.0f;

    for (int b = blockIdx.x; b < BSZ; b += ATTN_GRID) {
        const float* kb = K + (size_t)b * LSZ * DSZ;

        const float4* qkp = (const float4*)(g_QK + (size_t)b * DSZ + lane * 8);
        const float4 q0 = qkp[0];
        const float4 q1 = qkp[1];
        const int len = keys_length[b];

        float Z = 0.0f;
        float c0 = 0.f, c1 = 0.f, c2 = 0.f, c3 = 0.f;
        float c4 = 0.f, c5 = 0.f, c6 = 0.f, c7 = 0.f;

        #pragma unroll 5
        for (int i = 0; i < LSZ / 8; i++) {
            const int l = i * 8 + w;
            const float4* kr = (const float4*)(kb + l * DSZ + lane * 8);
            const float4 a0 = __ldg(kr);
            const float4 a1 = __ldg(kr + 1);

            float dot = a0.x * q0.x + a0.y * q0.y + a0.z * q0.z + a0.w * q0.w
                      + a1.x * q1.x + a1.y * q1.y + a1.z * q1.z + a1.w * q1.w;
            #pragma unroll
            for (int off = 16; off > 0; off >>= 1)
                dot += __shfl_xor_sync(0xffffffffu, dot, off);

            float p;
            if (len == 0) {
                p = 1.0f;
            } else if (l < len) {
                const float score = dot + b256;
                const float sig = 1.0f / (1.0f + __expf(-score));
                p = __expf(sig * 0.0625f - 0.0625f);
            } else {
                p = 0.0f;
            }

            Z += p;
            c0 += p * a0.x; c1 += p * a0.y; c2 += p * a0.z; c3 += p * a0.w;
            c4 += p * a1.x; c5 += p * a1.y; c6 += p * a1.z; c7 += p * a1.w;
        }

        if (lane == 0) sZ[w] = Z;
        const int d = lane * 8;
        sctx[w][d + 0] = c0; sctx[w][d + 1] = c1;
        sctx[w][d + 2] = c2; sctx[w][d + 3] = c3;
        sctx[w][d + 4] = c4; sctx[w][d + 5] = c5;
        sctx[w][d + 6] = c6; sctx[w][d + 7] = c7;
        __syncthreads();

        float zt = 0.0f;
        #pragma unroll
        for (int ww = 0; ww < 8; ww++) zt += sZ[ww];
        float c = 0.0f;
        #pragma unroll
        for (int ww = 0; ww < 8; ww++) c += sctx[ww][tid];

        g_CTX[(size_t)b * DSZ + tid] = c / zt;
        __syncthreads();   // protect sZ/sctx before next batch overwrites
    }
}

// ---------------------------------------------------------------------------
extern "C" void kernel_launch(void* const* d_in, const int* in_sizes, int n_in,
                              void* d_out, int out_size)
{
    const float* q      = (const float*)d_in[0];   // [2048, 1, 256]
    const float* k      = (const float*)d_in[1];   // [2048, 200, 256]
    // d_in[2] = v: unused (reference derives both score and value paths from k)
    const int*   klen   = (const int*)d_in[3];     // [2048, 1]
    const float* Wq     = (const float*)d_in[4];   // [256, 256]
    const float* Wk     = (const float*)d_in[5];   // [256, 256]
    const float* Wv     = (const float*)d_in[6];   // [256, 256]
    const float* bias   = (const float*)d_in[7];   // [1]
    float* out = (float*)d_out;                    // [2048, 1, 256]

    // 1) M = Wq @ Wk^T
    wmat_kernel<<<256, 256>>>(Wq, Wk);
    // 2) QK = q @ M   [2048,256]
    qk_gemm_kernel<<<dim3(BSZ / 32, DSZ / 32), 128>>>(q);
    // 3) attention in k-space -> CTX [2048,256]  (persistent, one wave)
    attn_kernel<<<ATTN_GRID, 256>>>(k, klen, bias);
    // 4) out = CTX @ Wv
    out_gemm_kernel<<<dim3(BSZ / 32, DSZ / 32), 128>>>(Wv, out);
}

// round 7
// speedup vs baseline: 1.4975x; 1.0683x over previous
#include <cuda_runtime.h>

#define BSZ 2048
#define LSZ 200
#define DSZ 256
#define NB  4               // batches per CTA
#define GRID (BSZ / NB)     // 512 CTAs -> ~3.5/SM at occ 4

// Scratch (device global — no allocation allowed).
__device__ float g_M[DSZ * DSZ];     // M = W_query @ W_key^T

// ---------------------------------------------------------------------------
// g_M[i][j] = Wq[i,:] . Wk[j,:]
// grid = 256 CTAs (one per output row i), 8 warps, warp w covers 32 cols.
// ---------------------------------------------------------------------------
__global__ void wmat_kernel(const float* __restrict__ Wq,
                            const float* __restrict__ Wk)
{
    const int i = blockIdx.x;
    const int w = threadIdx.x >> 5;
    const int lane = threadIdx.x & 31;

    const float4* ap = (const float4*)(Wq + i * 256 + lane * 8);
    const float4 a0 = ap[0];
    const float4 a1 = ap[1];

    float res = 0.0f;
    #pragma unroll 4
    for (int jj = 0; jj < 32; jj++) {
        const int j = w * 32 + jj;
        const float4* bp = (const float4*)(Wk + j * 256 + lane * 8);
        const float4 b0 = __ldg(bp);
        const float4 b1 = __ldg(bp + 1);
        float d = a0.x * b0.x + a0.y * b0.y + a0.z * b0.z + a0.w * b0.w
                + a1.x * b1.x + a1.y * b1.y + a1.z * b1.z + a1.w * b1.w;
        #pragma unroll
        for (int off = 16; off > 0; off >>= 1)
            d += __shfl_xor_sync(0xffffffffu, d, off);
        if (lane == jj) res = d;
    }
    g_M[i * 256 + w * 32 + lane] = res;
}

// ---------------------------------------------------------------------------
// Fused kernel: each CTA owns 4 consecutive batches [b0, b0+4).
//   prologue: QK rows = q rows @ M          (M L2-resident, coalesced reads)
//   main:     stream k once; fixed-max softmax in k-space -> CTX rows (smem)
//   epilogue: out rows = CTX rows @ Wv      (Wv L2-resident)
// QK/CTX never touch DRAM. Fixed-max softmax is exact: valid logits =
// sigmoid/16 in (0, 1/16]; masked PAD/16 underflows exp to exactly 0;
// len==0 (all PAD) -> uniform weights (p=1 for every l).
// ---------------------------------------------------------------------------
__global__ void __launch_bounds__(256, 4)
fused_attn_kernel(const float* __restrict__ q,
                  const float* __restrict__ K,
                  const int* __restrict__ keys_length,
                  const float* __restrict__ bias,
                  const float* __restrict__ Wv,
                  float* __restrict__ out)
{
    __shared__ float sq[NB * DSZ];    // q rows; reused as CTX rows after prologue
    __shared__ float sqk[NB * DSZ];   // QK rows
    __shared__ float sctx[8][DSZ];    // per-warp partial context
    __shared__ float sZ[8];           // per-warp partial normalizer

    const int tid = threadIdx.x;
    const int w = tid >> 5;
    const int lane = tid & 31;
    const int b0 = blockIdx.x * NB;
    const float b256 = bias[0] * 256.0f;

    // ---------------- prologue: sqk[bb][j] = sum_d q[b0+bb][d] * M[d][j]
    {
        const float4* src = (const float4*)(q + (size_t)b0 * DSZ);
        ((float4*)sq)[tid] = src[tid];          // 4 rows x 256 = 256 float4
        __syncthreads();

        float a0 = 0.f, a1 = 0.f, a2 = 0.f, a3 = 0.f;
        const float* Mc = g_M + tid;            // column tid, coalesced per d
        #pragma unroll 8
        for (int d = 0; d < DSZ; d++) {
            const float m = __ldg(Mc + (size_t)d * DSZ);
            a0 += sq[d] * m;
            a1 += sq[DSZ + d] * m;
            a2 += sq[2 * DSZ + d] * m;
            a3 += sq[3 * DSZ + d] * m;
        }
        sqk[tid] = a0;
        sqk[DSZ + tid] = a1;
        sqk[2 * DSZ + tid] = a2;
        sqk[3 * DSZ + tid] = a3;
        __syncthreads();                        // sqk ready; sq now free
    }

    // ---------------- main: attention per batch; CTX row -> sq[bb]
    #pragma unroll 1
    for (int bb = 0; bb < NB; bb++) {
        const int b = b0 + bb;
        const float* kb = K + (size_t)b * LSZ * DSZ;

        const float4 q0 = *(const float4*)&sqk[bb * DSZ + lane * 8];
        const float4 q1 = *(const float4*)&sqk[bb * DSZ + lane * 8 + 4];
        const int len = keys_length[b];

        float Z = 0.0f;
        float c0 = 0.f, c1 = 0.f, c2 = 0.f, c3 = 0.f;
        float c4 = 0.f, c5 = 0.f, c6 = 0.f, c7 = 0.f;

        #pragma unroll 5
        for (int i = 0; i < LSZ / 8; i++) {
            const int l = i * 8 + w;
            const float4* kr = (const float4*)(kb + l * DSZ + lane * 8);
            const float4 a0 = __ldg(kr);
            const float4 a1 = __ldg(kr + 1);

            float dot = a0.x * q0.x + a0.y * q0.y + a0.z * q0.z + a0.w * q0.w
                      + a1.x * q1.x + a1.y * q1.y + a1.z * q1.z + a1.w * q1.w;
            #pragma unroll
            for (int off = 16; off > 0; off >>= 1)
                dot += __shfl_xor_sync(0xffffffffu, dot, off);

            float p;
            if (len == 0) {
                p = 1.0f;                        // all masked -> uniform
            } else if (l < len) {
                const float score = dot + b256;
                const float sig = 1.0f / (1.0f + __expf(-score));
                p = __expf(sig * 0.0625f - 0.0625f);
            } else {
                p = 0.0f;                        // masked: exp underflows
            }

            Z += p;
            c0 += p * a0.x; c1 += p * a0.y; c2 += p * a0.z; c3 += p * a0.w;
            c4 += p * a1.x; c5 += p * a1.y; c6 += p * a1.z; c7 += p * a1.w;
        }

        if (lane == 0) sZ[w] = Z;   // Z identical across lanes after butterfly
        const int d = lane * 8;
        sctx[w][d + 0] = c0; sctx[w][d + 1] = c1;
        sctx[w][d + 2] = c2; sctx[w][d + 3] = c3;
        sctx[w][d + 4] = c4; sctx[w][d + 5] = c5;
        sctx[w][d + 6] = c6; sctx[w][d + 7] = c7;
        __syncthreads();

        float zt = 0.0f;
        #pragma unroll
        for (int ww = 0; ww < 8; ww++) zt += sZ[ww];
        float c = 0.0f;
        #pragma unroll
        for (int ww = 0; ww < 8; ww++) c += sctx[ww][tid];

        sq[bb * DSZ + tid] = c / zt;            // CTX row into smem
        __syncthreads();                        // protect sctx/sZ for next bb
    }

    // ---------------- epilogue: out[b0+bb][j] = sum_d CTX[bb][d] * Wv[d][j]
    {
        float a0 = 0.f, a1 = 0.f, a2 = 0.f, a3 = 0.f;
        const float* Wc = Wv + tid;             // column tid, coalesced per d
        #pragma unroll 8
        for (int d = 0; d < DSZ; d++) {
            const float v = __ldg(Wc + (size_t)d * DSZ);
            a0 += sq[d] * v;
            a1 += sq[DSZ + d] * v;
            a2 += sq[2 * DSZ + d] * v;
            a3 += sq[3 * DSZ + d] * v;
        }
        out[(size_t)(b0 + 0) * DSZ + tid] = a0;
        out[(size_t)(b0 + 1) * DSZ + tid] = a1;
        out[(size_t)(b0 + 2) * DSZ + tid] = a2;
        out[(size_t)(b0 + 3) * DSZ + tid] = a3;
    }
}

// ---------------------------------------------------------------------------
extern "C" void kernel_launch(void* const* d_in, const int* in_sizes, int n_in,
                              void* d_out, int out_size)
{
    const float* q      = (const float*)d_in[0];   // [2048, 1, 256]
    const float* k      = (const float*)d_in[1];   // [2048, 200, 256]
    // d_in[2] = v: unused (reference derives both score and value paths from k)
    const int*   klen   = (const int*)d_in[3];     // [2048, 1]
    const float* Wq     = (const float*)d_in[4];   // [256, 256]
    const float* Wk     = (const float*)d_in[5];   // [256, 256]
    const float* Wv     = (const float*)d_in[6];   // [256, 256]
    const float* bias   = (const float*)d_in[7];   // [1]
    float* out = (float*)d_out;                    // [2048, 1, 256]

    // 1) M = Wq @ Wk^T
    wmat_kernel<<<256, 256>>>(Wq, Wk);
    // 2) everything else, fused: QK -> attention -> out
    fused_attn_kernel<<<GRID, 256>>>(q, k, klen, bias, Wv, out);
}